// round 3
// baseline (speedup 1.0000x reference)
#include <cuda_runtime.h>

// FISTA box-constrained QP denoiser:
//   min ||y-x||^2 + LAM*||diff(x,2)||^2  s.t. 0 <= x <= y
// 100 iterations, applied twice (pass2 uses pass1 output as y).
// One warp per row of 512; 16 elements per lane held in registers;
// halo exchange via warp shuffles. No smem, no barriers, no global
// traffic inside the iteration loop.

#define NCOL 512
#define REG  16
#define NITER 100

__global__ void __launch_bounds__(256)
denoise_fista(const float* __restrict__ in, float* __restrict__ out, int nrows)
{
    const int gwarp = (int)((blockIdx.x * blockDim.x + threadIdx.x) >> 5);
    const int lane  = (int)(threadIdx.x & 31);
    if (gwarp >= nrows) return;

    const float LAM  = 10.0f;
    const float step = 1.0f / (2.0f * (1.0f + 16.0f * LAM));

    const float* __restrict__ src = in  + (size_t)gwarp * NCOL + lane * REG;
    float*       __restrict__ dst = out + (size_t)gwarp * NCOL + lane * REG;

    float y[REG], x[REG], z[REG];
#pragma unroll
    for (int q = 0; q < REG / 4; q++) {
        float4 v = *reinterpret_cast<const float4*>(src + 4 * q);
        y[4*q+0] = v.x; y[4*q+1] = v.y; y[4*q+2] = v.z; y[4*q+3] = v.w;
    }

#pragma unroll 1
    for (int pass = 0; pass < 2; pass++) {
        // x0 = proj(y) = clip(y, 0, y); z0 = x0; t = 1
#pragma unroll
        for (int j = 0; j < REG; j++) {
            x[j] = fminf(fmaxf(y[j], 0.0f), y[j]);
            z[j] = x[j];
        }
        float t = 1.0f;

#pragma unroll 1
        for (int k = 0; k < NITER; k++) {
            // ---- d = D z (second difference), d[gi] valid for gi <= N-3 ----
            float zn0 = __shfl_down_sync(0xffffffffu, z[0], 1);  // z[gi_base+16]
            float zn1 = __shfl_down_sync(0xffffffffu, z[1], 1);  // z[gi_base+17]
            float d[REG];
#pragma unroll
            for (int j = 0; j < REG - 2; j++)
                d[j] = z[j + 2] - 2.0f * z[j + 1] + z[j];
            d[REG - 2] = zn0 - 2.0f * z[REG - 1] + z[REG - 2];
            d[REG - 1] = zn1 - 2.0f * zn0 + z[REG - 1];
            if (lane == 31) { d[REG - 2] = 0.0f; d[REG - 1] = 0.0f; }

            // halo from previous lane for the adjoint pass
            float dp1 = __shfl_up_sync(0xffffffffu, d[REG - 1], 1); // d[gi_base-1]
            float dp0 = __shfl_up_sync(0xffffffffu, d[REG - 2], 1); // d[gi_base-2]
            if (lane == 0) { dp1 = 0.0f; dp0 = 0.0f; }

            // momentum scalar (uniform across lanes)
            float tn = 0.5f * (1.0f + sqrtf(1.0f + 4.0f * t * t));
            float c  = (t - 1.0f) / tn;
            t = tn;

            // ---- r = D^T d; gradient step; projection; momentum ----
#pragma unroll
            for (int j = 0; j < REG; j++) {
                float dm1 = (j >= 1) ? d[j - 1] : dp1;
                float dm2 = (j >= 2) ? d[j - 2] : ((j == 1) ? dp1 : dp0);
                // note: for j==1 the gi-2 entry is d[gi_base-1] = dp1
                if (j == 1) dm2 = dp1;
                float r  = d[j] - 2.0f * dm1 + dm2;
                float g  = 2.0f * (z[j] - y[j]) + (2.0f * LAM) * r;
                float v  = z[j] - step * g;
                float xn = fminf(fmaxf(v, 0.0f), y[j]);
                z[j] = xn + c * (xn - x[j]);
                x[j] = xn;
            }
        }

        if (pass == 0) {
            // y for pass 2 is pass-1 output; x0 = proj(y) = y handled by init above
#pragma unroll
            for (int j = 0; j < REG; j++) y[j] = x[j];
        }
    }

#pragma unroll
    for (int q = 0; q < REG / 4; q++) {
        float4 v = make_float4(x[4*q+0], x[4*q+1], x[4*q+2], x[4*q+3]);
        *reinterpret_cast<float4*>(dst + 4 * q) = v;
    }
}

extern "C" void kernel_launch(void* const* d_in, const int* in_sizes, int n_in,
                              void* d_out, int out_size)
{
    const float* in = (const float*)d_in[0];
    float* out = (float*)d_out;
    const int nrows = in_sizes[0] / NCOL;          // 32*512 = 16384 rows
    const int warps_per_block = 8;
    const int threads = warps_per_block * 32;      // 256
    const int blocks = (nrows + warps_per_block - 1) / warps_per_block;
    denoise_fista<<<blocks, threads>>>(in, out, nrows);
}

// round 9
// speedup vs baseline: 1.4902x; 1.4902x over previous
#include <cuda_runtime.h>

// FISTA box-QP denoiser, two passes of 100 iters.
// Fused 5-point D^T D stencil (exact via linear-extrapolated ghosts).
// TWO ROWS PER LANE packed into f32x2. Rolling old-value registers
// (zm1/zm2) fix the in-place stencil hazard from R4.

#define NCOL 512
#define REG  16
#define NITER 100

// ---- packed f32x2 helpers (sm_103a) ----
__device__ __forceinline__ float2 f2add(float2 a, float2 b) {
    float2 r;
    asm("{\n\t.reg .b64 A,B,R;\n\t"
        "mov.b64 A,{%2,%3};\n\tmov.b64 B,{%4,%5};\n\t"
        "add.rn.f32x2 R,A,B;\n\t"
        "mov.b64 {%0,%1},R;\n\t}"
        : "=f"(r.x), "=f"(r.y)
        : "f"(a.x), "f"(a.y), "f"(b.x), "f"(b.y));
    return r;
}
__device__ __forceinline__ float2 f2mul(float2 a, float2 b) {
    float2 r;
    asm("{\n\t.reg .b64 A,B,R;\n\t"
        "mov.b64 A,{%2,%3};\n\tmov.b64 B,{%4,%5};\n\t"
        "mul.rn.f32x2 R,A,B;\n\t"
        "mov.b64 {%0,%1},R;\n\t}"
        : "=f"(r.x), "=f"(r.y)
        : "f"(a.x), "f"(a.y), "f"(b.x), "f"(b.y));
    return r;
}
__device__ __forceinline__ float2 f2fma(float2 a, float2 b, float2 c) {
    float2 r;
    asm("{\n\t.reg .b64 A,B,C,R;\n\t"
        "mov.b64 A,{%2,%3};\n\tmov.b64 B,{%4,%5};\n\tmov.b64 C,{%6,%7};\n\t"
        "fma.rn.f32x2 R,A,B,C;\n\t"
        "mov.b64 {%0,%1},R;\n\t}"
        : "=f"(r.x), "=f"(r.y)
        : "f"(a.x), "f"(a.y), "f"(b.x), "f"(b.y), "f"(c.x), "f"(c.y));
    return r;
}

__device__ __forceinline__ float2 shup2(float2 v) {
    float2 r;
    r.x = __shfl_up_sync(0xffffffffu, v.x, 1);
    r.y = __shfl_up_sync(0xffffffffu, v.y, 1);
    return r;
}
__device__ __forceinline__ float2 shdn2(float2 v) {
    float2 r;
    r.x = __shfl_down_sync(0xffffffffu, v.x, 1);
    r.y = __shfl_down_sync(0xffffffffu, v.y, 1);
    return r;
}

__global__ void __launch_bounds__(128, 1)
denoise_fista2(const float* __restrict__ in, float* __restrict__ out, int nrows)
{
    const int gwarp = (int)((blockIdx.x * blockDim.x + threadIdx.x) >> 5);
    const int lane  = (int)(threadIdx.x & 31);
    const int r0 = 2 * gwarp;
    if (r0 >= nrows) return;

    const float LAM  = 10.0f;
    const float step = 1.0f / (2.0f * (1.0f + 16.0f * LAM));
    // v = (1-2s-12sL) z + 2s y - 2sL s1 + 8sL s2,  s1=z[i-2]+z[i+2], s2=z[i-1]+z[i+1]
    const float Ac = 1.0f - 2.0f * step - 12.0f * step * LAM;
    const float Bc = 2.0f * step;
    const float Cc = -2.0f * step * LAM;
    const float Dc = 8.0f * step * LAM;
    const float2 A2 = make_float2(Ac, Ac);
    const float2 B2 = make_float2(Bc, Bc);
    const float2 C2 = make_float2(Cc, Cc);
    const float2 D2 = make_float2(Dc, Dc);
    const float2 M1 = make_float2(-1.0f, -1.0f);

    const float* __restrict__ sa = in  + (size_t)r0 * NCOL + lane * REG;
    const float* __restrict__ sb = sa + NCOL;
    float*       __restrict__ da = out + (size_t)r0 * NCOL + lane * REG;
    float*       __restrict__ db = da + NCOL;

    float2 y[REG], x[REG], z[REG];
#pragma unroll
    for (int q = 0; q < REG / 4; q++) {
        float4 va = *reinterpret_cast<const float4*>(sa + 4 * q);
        float4 vb = *reinterpret_cast<const float4*>(sb + 4 * q);
        y[4*q+0] = make_float2(va.x, vb.x);
        y[4*q+1] = make_float2(va.y, vb.y);
        y[4*q+2] = make_float2(va.z, vb.z);
        y[4*q+3] = make_float2(va.w, vb.w);
    }

#pragma unroll 1
    for (int pass = 0; pass < 2; pass++) {
        // x0 = proj(y) = clip(y, 0, y); z0 = x0; t = 1
#pragma unroll
        for (int j = 0; j < REG; j++) {
            float2 p;
            p.x = fminf(fmaxf(y[j].x, 0.0f), y[j].x);
            p.y = fminf(fmaxf(y[j].y, 0.0f), y[j].y);
            x[j] = p; z[j] = p;
        }
        float t = 1.0f;

#pragma unroll 1
        for (int k = 0; k < NITER; k++) {
            // halos (all from OLD z): z[gi-1], z[gi-2], z[gi+16], z[gi+17]
            float2 zu1 = shup2(z[REG - 1]);
            float2 zu2 = shup2(z[REG - 2]);
            float2 zd1 = shdn2(z[0]);
            float2 zd2 = shdn2(z[1]);

            // ghost extrapolation at the two global ends:
            //   left:  z[-1] = 2 z0 - z1,   z[-2] = 2 z[-1] - z0
            //   right: z[n]  = 2 z[n-1] - z[n-2],  z[n+1] = 2 z[n] - z[n-1]
            {
                float2 e1 = f2fma(z[1], M1, f2add(z[0], z[0]));
                float2 e2 = f2fma(z[0], M1, f2add(e1, e1));
                if (lane == 0) { zu1 = e1; zu2 = e2; }
                float2 f1  = f2fma(z[REG - 2], M1, f2add(z[REG - 1], z[REG - 1]));
                float2 f2v = f2fma(z[REG - 1], M1, f2add(f1, f1));
                if (lane == 31) { zd1 = f1; zd2 = f2v; }
            }

            // momentum scalar (uniform across lanes & rows)
            float tn = 0.5f * (1.0f + sqrtf(1.0f + 4.0f * t * t));
            float c  = __fdividef(t - 1.0f, tn);
            t = tn;
            const float2 c2 = make_float2(c, c);

            // rolling OLD backward neighbors (fixes in-place hazard)
            float2 zm2 = zu2;
            float2 zm1 = zu1;

#pragma unroll
            for (int j = 0; j < REG; j++) {
                float2 np1 = (j <= REG - 2) ? z[j + 1] : zd1;
                float2 np2 = (j <= REG - 3) ? z[j + 2] : ((j == REG - 2) ? zd1 : zd2);

                float2 zc = z[j];                      // old center
                float2 s1 = f2add(zm2, np2);
                float2 s2 = f2add(zm1, np1);
                float2 w  = f2fma(s2, D2, f2mul(s1, C2));
                float2 v  = f2fma(zc, A2, f2fma(y[j], B2, w));

                float2 xn;
                xn.x = fminf(fmaxf(v.x, 0.0f), y[j].x);
                xn.y = fminf(fmaxf(v.y, 0.0f), y[j].y);

                float2 dz = f2fma(x[j], M1, xn);       // xn - x
                // roll old values BEFORE overwriting z[j]
                zm2 = zm1;
                zm1 = zc;
                z[j] = f2fma(dz, c2, xn);              // xn + c*(xn-x)
                x[j] = xn;
            }
        }

        if (pass == 0) {
#pragma unroll
            for (int j = 0; j < REG; j++) y[j] = x[j];
        }
    }

#pragma unroll
    for (int q = 0; q < REG / 4; q++) {
        float4 va = make_float4(x[4*q+0].x, x[4*q+1].x, x[4*q+2].x, x[4*q+3].x);
        float4 vb = make_float4(x[4*q+0].y, x[4*q+1].y, x[4*q+2].y, x[4*q+3].y);
        *reinterpret_cast<float4*>(da + 4 * q) = va;
        *reinterpret_cast<float4*>(db + 4 * q) = vb;
    }
}

extern "C" void kernel_launch(void* const* d_in, const int* in_sizes, int n_in,
                              void* d_out, int out_size)
{
    const float* in = (const float*)d_in[0];
    float* out = (float*)d_out;
    const int nrows = in_sizes[0] / NCOL;             // 16384 rows
    const int nwarps = nrows / 2;                     // 2 rows per warp
    const int warps_per_block = 4;
    const int threads = warps_per_block * 32;         // 128
    const int blocks = (nwarps + warps_per_block - 1) / warps_per_block;
    denoise_fista2<<<blocks, threads>>>(in, out, nrows);
}